// round 17
// baseline (speedup 1.0000x reference)
#include <cuda_runtime.h>
#include <cuda_bf16.h>

// Problem constants
#define BB 16
#define LL 512
#define HS 1024
#define HH 16
#define DD 64
#define MROWS (BB*LL)        // 8192

// -------------------- scratch (allocation-free) --------------------
__device__ float g_vh[BB*HH*LL*DD];   // [B,H,L,D]
__device__ float g_kh[BB*HH*LL*DD];
__device__ float g_qh[BB*HH*LL*DD];
__device__ unsigned char g_absm8[BB*LL*LL];
__device__ unsigned char g_mask8[BB*LL*LL];
__device__ uint4 g_inhi[3L*MROWS*HS/8];
__device__ uint4 g_inlo[3L*MROWS*HS/8];
__device__ uint4 g_whi[4L*HS*HS/8];
__device__ uint4 g_wlo[4L*HS*HS/8];
__device__ uint4 g_atthi[(long)MROWS*HS/8];
__device__ uint4 g_attlo[(long)MROWS*HS/8];

// Q pre-scale: 0.125 (1/sqrt(64)) * log2(e)  -> softmax done in exp2 domain
#define QSCALE 0.1803368801111244f

// ------------------ bf16 helpers ------------------
__device__ __forceinline__ unsigned pack2bf(__nv_bfloat16 a, __nv_bfloat16 b) {
    __nv_bfloat162 t; t.x = a; t.y = b;
    return reinterpret_cast<unsigned&>(t);
}

__device__ __forceinline__ void bsplit2(float x0, float x1, unsigned &hi, unsigned &lo) {
    __nv_bfloat16 h0 = __float2bfloat16(x0);
    __nv_bfloat16 h1 = __float2bfloat16(x1);
    __nv_bfloat16 l0 = __float2bfloat16(x0 - __bfloat162float(h0));
    __nv_bfloat16 l1 = __float2bfloat16(x1 - __bfloat162float(h1));
    hi = pack2bf(h0, h1);
    lo = pack2bf(l0, l1);
}

__device__ __forceinline__ void mma_bf16(float d[4],
                                         unsigned a0, unsigned a1, unsigned a2, unsigned a3,
                                         unsigned b0, unsigned b1)
{
    asm volatile(
        "mma.sync.aligned.m16n8k16.row.col.f32.bf16.bf16.f32 "
        "{%0,%1,%2,%3}, {%4,%5,%6,%7}, {%8,%9}, {%0,%1,%2,%3};\n"
        : "+f"(d[0]), "+f"(d[1]), "+f"(d[2]), "+f"(d[3])
        : "r"(a0), "r"(a1), "r"(a2), "r"(a3), "r"(b0), "r"(b1));
}

__device__ __forceinline__ float fexp2(float x) {
    float y;
    asm("ex2.approx.f32 %0, %1;" : "=f"(y) : "f"(x));
    return y;
}

__device__ __forceinline__ void cp16(void* smem_dst, const void* gmem_src) {
    unsigned s = (unsigned)__cvta_generic_to_shared(smem_dst);
    asm volatile("cp.async.cg.shared.global [%0], [%1], 16;\n"
                 :: "r"(s), "l"(gmem_src) : "memory");
}
#define CP_COMMIT() asm volatile("cp.async.commit_group;\n" ::: "memory")
#define CP_WAIT(n)  asm volatile("cp.async.wait_group %0;\n" :: "n"(n) : "memory")

// ====================================================================
// Prepack kernels
// ====================================================================
__global__ void __launch_bounds__(256) pack_masks(const uint4* __restrict__ a,
                                                  const uint4* __restrict__ b,
                                                  uchar4* __restrict__ oa,
                                                  uchar4* __restrict__ ob)
{
    int i = blockIdx.x * blockDim.x + threadIdx.x;
    uint4 x = a[i];
    oa[i] = make_uchar4(x.x ? 1 : 0, x.y ? 1 : 0, x.z ? 1 : 0, x.w ? 1 : 0);
    uint4 y = b[i];
    ob[i] = make_uchar4(y.x ? 1 : 0, y.y ? 1 : 0, y.z ? 1 : 0, y.w ? 1 : 0);
}

__global__ void __launch_bounds__(256) pack_in(const float4* __restrict__ v,
                                               const float4* __restrict__ k,
                                               const float4* __restrict__ q)
{
    int z = blockIdx.y;
    const float4* src = (z == 0) ? v : (z == 1) ? k : q;
    long i = (long)blockIdx.x * 256 + threadIdx.x;
    float4 x = src[i];
    unsigned h01, l01, h23, l23;
    bsplit2(x.x, x.y, h01, l01);
    bsplit2(x.z, x.w, h23, l23);
    long d = (long)z * (MROWS * (long)HS / 4) + i;
    ((uint2*)g_inhi)[d] = make_uint2(h01, h23);
    ((uint2*)g_inlo)[d] = make_uint2(l01, l23);
}

__global__ void __launch_bounds__(256) pack_w(const float4* __restrict__ w0,
                                              const float4* __restrict__ w1,
                                              const float4* __restrict__ w2,
                                              const float4* __restrict__ w3)
{
    int z = blockIdx.y;
    const float4* src = (z == 0) ? w0 : (z == 1) ? w1 : (z == 2) ? w2 : w3;
    long i = (long)blockIdx.x * 256 + threadIdx.x;
    float4 x = src[i];
    unsigned h01, l01, h23, l23;
    bsplit2(x.x, x.y, h01, l01);
    bsplit2(x.z, x.w, h23, l23);
    long d = (long)z * ((long)HS * HS / 4) + i;
    ((uint2*)g_whi)[d] = make_uint2(h01, h23);
    ((uint2*)g_wlo)[d] = make_uint2(l01, l23);
}

// ====================================================================
// bf16 GEMM (R13 config, GEMM plateau): 128x128 tile, cp.async, 2 CTAs/SM.
// ====================================================================
#define BP 40
#define STG (4*128*BP)

template<int GEMM3>
__global__ void __launch_bounds__(256, 2) gemm_pre(float* __restrict__ Cout,
                                                   int M, int N, int K)
{
    extern __shared__ float smf[];
    __nv_bfloat16* smb = (__nv_bfloat16*)smf;

    const __nv_bfloat16 *Ahi, *Alo, *Whi, *Wlo;
    float* C;
    if (GEMM3) {
        int z = blockIdx.z;
        Ahi = (const __nv_bfloat16*)g_inhi + (long)z * MROWS * HS;
        Alo = (const __nv_bfloat16*)g_inlo + (long)z * MROWS * HS;
        Whi = (const __nv_bfloat16*)g_whi + (long)z * HS * HS;
        Wlo = (const __nv_bfloat16*)g_wlo + (long)z * HS * HS;
        C   = (z == 0) ? g_vh : (z == 1) ? g_kh : g_qh;
    } else {
        Ahi = (const __nv_bfloat16*)g_atthi;
        Alo = (const __nv_bfloat16*)g_attlo;
        Whi = (const __nv_bfloat16*)g_whi + 3L * HS * HS;
        Wlo = (const __nv_bfloat16*)g_wlo + 3L * HS * HS;
        C   = Cout;
    }

    const int tid  = threadIdx.x;
    const int br   = blockIdx.y;
    const int bc   = blockIdx.x;
    const int wid  = tid >> 5;
    const int lane = tid & 31;
    const int g    = lane >> 2;
    const int tig  = lane & 3;
    const int wm   = wid >> 2;
    const int wn   = wid & 3;

    const __nv_bfloat16* AbH = Ahi + (long)br * 128 * K;
    const __nv_bfloat16* AbL = Alo + (long)br * 128 * K;
    const __nv_bfloat16* BbH = Whi + (long)bc * 128 * K;
    const __nv_bfloat16* BbL = Wlo + (long)bc * 128 * K;

    float acc[4][4][4];
#pragma unroll
    for (int mt = 0; mt < 4; ++mt)
#pragma unroll
        for (int nt = 0; nt < 4; ++nt)
#pragma unroll
            for (int r = 0; r < 4; ++r) acc[mt][nt][r] = 0.f;

    auto issue = [&](int s, int kb) {
        __nv_bfloat16* AsHi = smb + s * STG;
        __nv_bfloat16* AsLo = AsHi + 128 * BP;
        __nv_bfloat16* BsHi = AsLo + 128 * BP;
        __nv_bfloat16* BsLo = BsHi + 128 * BP;
#pragma unroll
        for (int i = 0; i < 2; ++i) {
            int ch = tid + i * 256;
            int row = ch >> 2, seg = ch & 3;
            long go = (long)row * K + kb + seg * 8;
            int  so = row * BP + seg * 8;
            cp16(AsHi + so, AbH + go);
            cp16(AsLo + so, AbL + go);
            cp16(BsHi + so, BbH + go);
            cp16(BsLo + so, BbL + go);
        }
        CP_COMMIT();
    };

    issue(0, 0);

    const int nKt = K / 32;
    for (int kt = 0; kt < nKt; ++kt) {
        const int s = kt & 1;
        if (kt + 1 < nKt) {
            issue(s ^ 1, (kt + 1) * 32);
            CP_WAIT(1);
        } else {
            CP_WAIT(0);
        }
        __syncthreads();

        const __nv_bfloat16* AsHi = smb + s * STG;
        const __nv_bfloat16* AsLo = AsHi + 128 * BP;
        const __nv_bfloat16* BsHi = AsLo + 128 * BP;
        const __nv_bfloat16* BsLo = BsHi + 128 * BP;

#pragma unroll
        for (int ks = 0; ks < 2; ++ks) {
            const int kk = ks * 16;
            unsigned ah[4][4], al[4][4];
#pragma unroll
            for (int mt = 0; mt < 4; ++mt) {
                int m = wm * 64 + mt * 16 + g;
                const __nv_bfloat16* pH = AsHi + m * BP + kk + tig * 2;
                const __nv_bfloat16* pL = AsLo + m * BP + kk + tig * 2;
                ah[mt][0] = *(const unsigned*)(pH);
                ah[mt][1] = *(const unsigned*)(pH + 8 * BP);
                ah[mt][2] = *(const unsigned*)(pH + 8);
                ah[mt][3] = *(const unsigned*)(pH + 8 * BP + 8);
                al[mt][0] = *(const unsigned*)(pL);
                al[mt][1] = *(const unsigned*)(pL + 8 * BP);
                al[mt][2] = *(const unsigned*)(pL + 8);
                al[mt][3] = *(const unsigned*)(pL + 8 * BP + 8);
            }
#pragma unroll
            for (int nt = 0; nt < 4; ++nt) {
                int n = wn * 32 + nt * 8 + g;
                const __nv_bfloat16* pH = BsHi + n * BP + kk + tig * 2;
                const __nv_bfloat16* pL = BsLo + n * BP + kk + tig * 2;
                unsigned bh0 = *(const unsigned*)(pH);
                unsigned bh1 = *(const unsigned*)(pH + 8);
                unsigned bl0 = *(const unsigned*)(pL);
                unsigned bl1 = *(const unsigned*)(pL + 8);
#pragma unroll
                for (int mt = 0; mt < 4; ++mt) {
                    mma_bf16(acc[mt][nt], ah[mt][0], ah[mt][1], ah[mt][2], ah[mt][3],
                             bh0, bh1);
                    mma_bf16(acc[mt][nt], al[mt][0], al[mt][1], al[mt][2], al[mt][3],
                             bh0, bh1);
                    mma_bf16(acc[mt][nt], ah[mt][0], ah[mt][1], ah[mt][2], ah[mt][3],
                             bl0, bl1);
                }
            }
        }
        __syncthreads();
    }

#pragma unroll
    for (int mt = 0; mt < 4; ++mt) {
#pragma unroll
        for (int nt = 0; nt < 4; ++nt) {
            int jj = bc * 128 + wn * 32 + nt * 8 + tig * 2;
#pragma unroll
            for (int half = 0; half < 2; ++half) {
                int ii = br * 128 + wm * 64 + mt * 16 + g + half * 8;
                float2 val;
                val.x = acc[mt][nt][half * 2 + 0];
                val.y = acc[mt][nt][half * 2 + 1];
                if (GEMM3 == 0) {
                    *(float2*)(C + (long)ii * N + jj) = val;
                } else {
                    int b = ii >> 9, l = ii & 511;
                    int h = jj >> 6, d = jj & 63;
                    *(float2*)(C + (((long)(b * 16 + h) * 512) + l) * 64 + d) = val;
                }
            }
        }
    }
}

// ====================================================================
// FUSED two-stage tensor-core flash attention (all-bf16 3-term).
// R17: double-buffered K/V/mask smem tiles — one __syncthreads per tile
// (16 total, was 32), and the cvt+STS store phase for tile g+1 is issued
// between softmax and PV of tile g so it interleaves with tensor ops.
// ====================================================================
#define KP  72
#define VTP 36
#define QSP 68
#define BUF_FLOATS 11264        // 45056 B per buffer
// float offsets within a buffer
#define BO_KHI 0
#define BO_KLO 2304
#define BO_VTH 4608
#define BO_VTL 6912
#define BO_MS  9216             // 8192 B of mask bytes
#define ATTN_SMEM_FLOATS (2*BUF_FLOATS)   // 90112 B; Q staging aliases buf1

__global__ void __launch_bounds__(256, 1) attn_fused(
    const float* __restrict__ Qg,          // g_qh [B,H,L,D]
    const float* __restrict__ img,         // [B,L,HS]
    const unsigned char* __restrict__ absm8,
    const float* __restrict__ kh,          // [B,H,L,D]
    const float* __restrict__ vh,          // [B,H,L,D]
    const unsigned char* __restrict__ mask8)
{
    extern __shared__ float sm[];
    float* Qs = sm + BUF_FLOATS;           // staging aliases buffer 1

    const int b  = blockIdx.z;
    const int h  = blockIdx.y;
    const int q0 = blockIdx.x * 128;

    const float* Qp  = Qg + (((long)(b*16 + h) * 512) + q0) * 64;
    const float* Kbase[2];
    const float* Vbase[2];
    const unsigned char* Mbase[2];
    int rstride[2];
    Kbase[0] = img + (long)b * LL * HS + h * 64;   rstride[0] = HS;
    Vbase[0] = Kbase[0];
    Mbase[0] = absm8 + (long)b * LL * LL + (long)q0 * LL;
    Kbase[1] = kh + (((long)(b*16 + h) * 512)) * 64;  rstride[1] = DD;
    Vbase[1] = vh + (((long)(b*16 + h) * 512)) * 64;
    Mbase[1] = mask8 + (long)b * LL * LL + (long)q0 * LL;

    __nv_bfloat16* OHi = (__nv_bfloat16*)g_atthi + (long)b * LL * HS + h * 64 + (long)q0 * HS;
    __nv_bfloat16* OLo = (__nv_bfloat16*)g_attlo + (long)b * LL * HS + h * 64 + (long)q0 * HS;

    const int tid  = threadIdx.x;
    const int w    = tid >> 5;
    const int lane = tid & 31;
    const int g    = lane >> 2;
    const int tig  = lane & 3;
    const int r0   = w * 16 + g;

    const int kf_row[4] = { (tid) >> 4, (tid + 256) >> 4, (tid + 512) >> 4, (tid + 768) >> 4 };
    const int kf_c4 = tid & 15;
    const int vjp0 = tid & 31, vc40 = tid >> 5;
    const int vjp1 = vjp0, vc41 = vc40 + 8;

    // ---- stage Q, extract bf16 hi/lo fragments (QSCALE folded) ----
#pragma unroll
    for (int it = 0; it < 8; ++it) {
        int f = tid + it * 256;
        int row = f >> 4, c4 = f & 15;
        float4 v = *(const float4*)(Qp + (long)row * 64 + c4 * 4);
        float* dst = Qs + row * QSP + c4 * 4;
        dst[0] = v.x; dst[1] = v.y; dst[2] = v.z; dst[3] = v.w;
    }
    __syncthreads();

    unsigned qh[4][4], ql[4][4];
#pragma unroll
    for (int kc = 0; kc < 4; ++kc) {
        const float* p0 = Qs + (r0)     * QSP + kc * 16 + tig * 2;
        const float* p1 = Qs + (r0 + 8) * QSP + kc * 16 + tig * 2;
        bsplit2(p0[0] * QSCALE, p0[1] * QSCALE, qh[kc][0], ql[kc][0]);
        bsplit2(p1[0] * QSCALE, p1[1] * QSCALE, qh[kc][1], ql[kc][1]);
        bsplit2(p0[8] * QSCALE, p0[9] * QSCALE, qh[kc][2], ql[kc][2]);
        bsplit2(p1[8] * QSCALE, p1[9] * QSCALE, qh[kc][3], ql[kc][3]);
    }
    __syncthreads();   // all frag reads of Qs (buf1 alias) done before buf1 is written

    float oacc[8][4];
#pragma unroll
    for (int nt = 0; nt < 8; ++nt)
#pragma unroll
        for (int i = 0; i < 4; ++i) oacc[nt][i] = 0.f;

    float m0 = -1e30f, m1 = -1e30f, l0 = 0.f, l1 = 0.f;

    float4 pk[4];
    float4 pva[2], pvb[2];
    uint4  pm[2];

    auto prefetch = [&](int ph, int k0) {
        const float* Kp = Kbase[ph];
        const float* Vp = Vbase[ph];
        const unsigned char* Mp = Mbase[ph];
        const int rs = rstride[ph];
#pragma unroll
        for (int it = 0; it < 4; ++it)
            pk[it] = *(const float4*)(Kp + (long)(k0 + kf_row[it]) * rs + kf_c4 * 4);
        {
            const float* v0 = Vp + (long)(k0 + 2 * vjp0) * rs + vc40 * 4;
            pva[0] = *(const float4*)v0;
            pvb[0] = *(const float4*)(v0 + rs);
            const float* v1 = Vp + (long)(k0 + 2 * vjp1) * rs + vc41 * 4;
            pva[1] = *(const float4*)v1;
            pvb[1] = *(const float4*)(v1 + rs);
        }
#pragma unroll
        for (int it = 0; it < 2; ++it) {
            int u = tid + it * 256;
            int row = u >> 2, c16 = u & 3;
            pm[it] = *(const uint4*)(Mp + (long)row * LL + k0 + c16 * 16);
        }
    };

    auto store_tile = [&](int buf) {
        float* base = sm + buf * BUF_FLOATS;
        __nv_bfloat16* Khi = (__nv_bfloat16*)(base + BO_KHI);
        __nv_bfloat16* Klo = (__nv_bfloat16*)(base + BO_KLO);
        unsigned* VtHi = (unsigned*)(base + BO_VTH);
        unsigned* VtLo = (unsigned*)(base + BO_VTL);
        unsigned char* Ms = (unsigned char*)(base + BO_MS);
#pragma unroll
        for (int it = 0; it < 4; ++it) {
            int row = kf_row[it];
            unsigned h01, l01, h23, l23;
            bsplit2(pk[it].x, pk[it].y, h01, l01);
            bsplit2(pk[it].z, pk[it].w, h23, l23);
            *(uint2*)(Khi + row * KP + kf_c4 * 4) = make_uint2(h01, h23);
            *(uint2*)(Klo + row * KP + kf_c4 * 4) = make_uint2(l01, l23);
        }
#pragma unroll
        for (int it = 0; it < 2; ++it) {
            int jp = (it == 0) ? vjp0 : vjp1;
            int c4 = (it == 0) ? vc40 : vc41;
            float4 a = pva[it], bq = pvb[it];
            unsigned hh, ll;
            bsplit2(a.x, bq.x, hh, ll);
            VtHi[(c4 * 4 + 0) * VTP + jp] = hh; VtLo[(c4 * 4 + 0) * VTP + jp] = ll;
            bsplit2(a.y, bq.y, hh, ll);
            VtHi[(c4 * 4 + 1) * VTP + jp] = hh; VtLo[(c4 * 4 + 1) * VTP + jp] = ll;
            bsplit2(a.z, bq.z, hh, ll);
            VtHi[(c4 * 4 + 2) * VTP + jp] = hh; VtLo[(c4 * 4 + 2) * VTP + jp] = ll;
            bsplit2(a.w, bq.w, hh, ll);
            VtHi[(c4 * 4 + 3) * VTP + jp] = hh; VtLo[(c4 * 4 + 3) * VTP + jp] = ll;
        }
#pragma unroll
        for (int it = 0; it < 2; ++it) {
            int u = tid + it * 256;
            int row = u >> 2, c16 = u & 3;
            ((uint4*)Ms)[row * 4 + c16] = pm[it];
        }
    };

    // prologue: tile 0 into buf0
    prefetch(0, 0);
    store_tile(0);
    __syncthreads();

    for (int phase = 0; phase < 2; ++phase) {
        for (int kt = 0; kt < 8; ++kt) {
            const int gidx = phase * 8 + kt;
            const int buf  = gidx & 1;
            const bool has_next = (gidx + 1 < 16);

            // issue next tile's global loads early
            if (kt + 1 < 8)          prefetch(phase, (kt + 1) * 64);
            else if (phase == 0)     prefetch(1, 0);

            float* base = sm + buf * BUF_FLOATS;
            const __nv_bfloat16* Khi = (const __nv_bfloat16*)(base + BO_KHI);
            const __nv_bfloat16* Klo = (const __nv_bfloat16*)(base + BO_KLO);
            const unsigned* VtHi = (const unsigned*)(base + BO_VTH);
            const unsigned* VtLo = (const unsigned*)(base + BO_VTL);
            const unsigned char* Ms = (const unsigned char*)(base + BO_MS);

            // ---- S = Q K^T (3-term bf16, exp2 domain) ----
            float sacc[8][4];
#pragma unroll
            for (int nt = 0; nt < 8; ++nt) {
#pragma unroll
                for (int i = 0; i < 4; ++i) sacc[nt][i] = 0.f;
#pragma unroll
                for (int kc = 0; kc < 4; ++kc) {
                    const __nv_bfloat16* pH = Khi + (nt * 8 + g) * KP + kc * 16 + tig * 2;
                    const __nv_bfloat16* pL = Klo + (nt * 8 + g) * KP + kc * 16 + tig * 2;
                    unsigned bh0 = *(const unsigned*)(pH);
                    unsigned bh1 = *(const unsigned*)(pH + 8);
                    unsigned bl0 = *(const unsigned*)(pL);
                    unsigned bl1 = *(const unsigned*)(pL + 8);
                    mma_bf16(sacc[nt], qh[kc][0], qh[kc][1], qh[kc][2], qh[kc][3], bh0, bh1);
                    mma_bf16(sacc[nt], ql[kc][0], ql[kc][1], ql[kc][2], ql[kc][3], bh0, bh1);
                    mma_bf16(sacc[nt], qh[kc][0], qh[kc][1], qh[kc][2], qh[kc][3], bl0, bl1);
                }
            }

            // ---- mask ----
#pragma unroll
            for (int nt = 0; nt < 8; ++nt) {
                uchar2 mA = *(const uchar2*)(Ms + (r0)     * 64 + nt * 8 + tig * 2);
                uchar2 mB = *(const uchar2*)(Ms + (r0 + 8) * 64 + nt * 8 + tig * 2);
                if (mA.x) sacc[nt][0] = -1e9f;
                if (mA.y) sacc[nt][1] = -1e9f;
                if (mB.x) sacc[nt][2] = -1e9f;
                if (mB.y) sacc[nt][3] = -1e9f;
            }

            // ---- online softmax (warp-local, exp2) ----
            float mx0 = -3.0e38f, mx1 = -3.0e38f;
#pragma unroll
            for (int nt = 0; nt < 8; ++nt) {
                mx0 = fmaxf(mx0, fmaxf(sacc[nt][0], sacc[nt][1]));
                mx1 = fmaxf(mx1, fmaxf(sacc[nt][2], sacc[nt][3]));
            }
            mx0 = fmaxf(mx0, __shfl_xor_sync(0xffffffffu, mx0, 1));
            mx0 = fmaxf(mx0, __shfl_xor_sync(0xffffffffu, mx0, 2));
            mx1 = fmaxf(mx1, __shfl_xor_sync(0xffffffffu, mx1, 1));
            mx1 = fmaxf(mx1, __shfl_xor_sync(0xffffffffu, mx1, 2));

            float mn0 = fmaxf(m0, mx0), mn1 = fmaxf(m1, mx1);
            float al0 = fexp2(m0 - mn0), al1 = fexp2(m1 - mn1);
            m0 = mn0; m1 = mn1;

            unsigned pfh[8][2], pfl[8][2];
            float sum0 = 0.f, sum1 = 0.f;
#pragma unroll
            for (int nt = 0; nt < 8; ++nt) {
                float p00 = fexp2(sacc[nt][0] - m0);
                float p01 = fexp2(sacc[nt][1] - m0);
                float p10 = fexp2(sacc[nt][2] - m1);
                float p11 = fexp2(sacc[nt][3] - m1);
                sum0 += p00 + p01;
                sum1 += p10 + p11;
                bsplit2(p00, p01, pfh[nt][0], pfl[nt][0]);
                bsplit2(p10, p11, pfh[nt][1], pfl[nt][1]);
            }
            sum0 += __shfl_xor_sync(0xffffffffu, sum0, 1);
            sum0 += __shfl_xor_sync(0xffffffffu, sum0, 2);
            sum1 += __shfl_xor_sync(0xffffffffu, sum1, 1);
            sum1 += __shfl_xor_sync(0xffffffffu, sum1, 2);
            l0 = l0 * al0 + sum0;
            l1 = l1 * al1 + sum1;

#pragma unroll
            for (int nt = 0; nt < 8; ++nt) {
                oacc[nt][0] *= al0; oacc[nt][1] *= al0;
                oacc[nt][2] *= al1; oacc[nt][3] *= al1;
            }

            // ---- store NEXT tile into the other buffer (interleaves with PV) ----
            if (has_next) store_tile(buf ^ 1);

            // ---- O += P V (3-term bf16, P from registers) ----
#pragma unroll
            for (int kc = 0; kc < 4; ++kc) {
                unsigned ph0 = pfh[2*kc][0],   ph1 = pfh[2*kc][1];
                unsigned ph2 = pfh[2*kc+1][0], ph3 = pfh[2*kc+1][1];
                unsigned pl0 = pfl[2*kc][0],   pl1 = pfl[2*kc][1];
                unsigned pl2 = pfl[2*kc+1][0], pl3 = pfl[2*kc+1][1];
#pragma unroll
                for (int nt = 0; nt < 8; ++nt) {
                    const unsigned* vH = VtHi + (nt * 8 + g) * VTP + kc * 8 + tig;
                    const unsigned* vL = VtLo + (nt * 8 + g) * VTP + kc * 8 + tig;
                    unsigned bh0 = vH[0], bh1 = vH[4];
                    unsigned bl0 = vL[0], bl1 = vL[4];
                    mma_bf16(oacc[nt], ph0, ph1, ph2, ph3, bh0, bh1);
                    mma_bf16(oacc[nt], pl0, pl1, pl2, pl3, bh0, bh1);
                    mma_bf16(oacc[nt], ph0, ph1, ph2, ph3, bl0, bl1);
                }
            }
            __syncthreads();

            if (phase == 0 && kt == 7) {
                // ---- inter-stage: qn = oacc/l + Q residual, rebuild Q frags ----
                float inv0 = 1.0f / l0, inv1 = 1.0f / l1;
                float qn0[8][2], qn1[8][2];
#pragma unroll
                for (int nt = 0; nt < 8; ++nt) {
                    int c = nt * 8 + tig * 2;
                    float2 qr0 = *(const float2*)(Qp + (long)(r0)     * 64 + c);
                    float2 qr1 = *(const float2*)(Qp + (long)(r0 + 8) * 64 + c);
                    qn0[nt][0] = oacc[nt][0] * inv0 + qr0.x;
                    qn0[nt][1] = oacc[nt][1] * inv0 + qr0.y;
                    qn1[nt][0] = oacc[nt][2] * inv1 + qr1.x;
                    qn1[nt][1] = oacc[nt][3] * inv1 + qr1.y;
                }
#pragma unroll
                for (int kc = 0; kc < 4; ++kc) {
                    bsplit2(qn0[2*kc][0]   * QSCALE, qn0[2*kc][1]   * QSCALE, qh[kc][0], ql[kc][0]);
                    bsplit2(qn1[2*kc][0]   * QSCALE, qn1[2*kc][1]   * QSCALE, qh[kc][1], ql[kc][1]);
                    bsplit2(qn0[2*kc+1][0] * QSCALE, qn0[2*kc+1][1] * QSCALE, qh[kc][2], ql[kc][2]);
                    bsplit2(qn1[2*kc+1][0] * QSCALE, qn1[2*kc+1][1] * QSCALE, qh[kc][3], ql[kc][3]);
                }
                m0 = -1e30f; m1 = -1e30f; l0 = 0.f; l1 = 0.f;
#pragma unroll
                for (int nt = 0; nt < 8; ++nt)
#pragma unroll
                    for (int i = 0; i < 4; ++i) oacc[nt][i] = 0.f;
            }
        }
    }

    // ---- epilogue: bf16 hi/lo to g_att{hi,lo} [B,L,H*D] ----
    float inv0 = 1.0f / l0, inv1 = 1.0f / l1;
#pragma unroll
    for (int nt = 0; nt < 8; ++nt) {
        int c = nt * 8 + tig * 2;
        unsigned hh, ll;
        bsplit2(oacc[nt][0] * inv0, oacc[nt][1] * inv0, hh, ll);
        *(unsigned*)(OHi + (long)(r0) * HS + c) = hh;
        *(unsigned*)(OLo + (long)(r0) * HS + c) = ll;
        bsplit2(oacc[nt][2] * inv1, oacc[nt][3] * inv1, hh, ll);
        *(unsigned*)(OHi + (long)(r0 + 8) * HS + c) = hh;
        *(unsigned*)(OLo + (long)(r0 + 8) * HS + c) = ll;
    }
}

// ====================================================================
extern "C" void kernel_launch(void* const* d_in, const int* in_sizes, int n_in,
                              void* d_out, int out_size)
{
    (void)in_sizes; (void)n_in; (void)out_size;
    const float* v   = (const float*)d_in[0];
    const float* k   = (const float*)d_in[1];
    const float* q   = (const float*)d_in[2];
    const float* img = (const float*)d_in[3];
    const float* Wv  = (const float*)d_in[4];
    const float* Wk  = (const float*)d_in[5];
    const float* Wq  = (const float*)d_in[6];
    const float* Wm  = (const float*)d_in[7];
    const uint4* absm = (const uint4*)d_in[8];
    const uint4* mask = (const uint4*)d_in[9];
    float* out = (float*)d_out;

    float *vh, *kh, *qh;
    unsigned char *absm8, *mask8;
    cudaGetSymbolAddress((void**)&vh,  g_vh);
    cudaGetSymbolAddress((void**)&kh,  g_kh);
    cudaGetSymbolAddress((void**)&qh,  g_qh);
    cudaGetSymbolAddress((void**)&absm8, g_absm8);
    cudaGetSymbolAddress((void**)&mask8, g_mask8);

    pack_masks<<<4096, 256>>>(absm, mask, (uchar4*)absm8, (uchar4*)mask8);
    dim3 gi(MROWS * HS / 4 / 256, 3);
    pack_in<<<gi, 256>>>((const float4*)v, (const float4*)k, (const float4*)q);
    dim3 gw(HS * HS / 4 / 256, 4);
    pack_w<<<gw, 256>>>((const float4*)Wv, (const float4*)Wk,
                        (const float4*)Wq, (const float4*)Wm);

    const int gsmem = 2 * STG * (int)sizeof(__nv_bfloat16);   // 81920
    cudaFuncSetAttribute(gemm_pre<0>,
                         cudaFuncAttributeMaxDynamicSharedMemorySize, gsmem);
    cudaFuncSetAttribute(gemm_pre<1>,
                         cudaFuncAttributeMaxDynamicSharedMemorySize, gsmem);

    dim3 g3(HS / 128, MROWS / 128, 3);   // (8, 64, 3)
    gemm_pre<1><<<g3, 256, gsmem>>>(nullptr, MROWS, HS, HS);

    const int asmem = ATTN_SMEM_FLOATS * (int)sizeof(float);  // 90112
    cudaFuncSetAttribute(attn_fused,
                         cudaFuncAttributeMaxDynamicSharedMemorySize, asmem);

    dim3 ga(LL / 128, HH, BB);   // (4, 16, 16)
    attn_fused<<<ga, 256, asmem>>>(qh, img, absm8, kh, vh, mask8);

    dim3 gg(HS / 128, MROWS / 128);   // (8, 64)
    gemm_pre<0><<<gg, 256, gsmem>>>(out, MROWS, HS, HS);
}